// round 16
// baseline (speedup 1.0000x reference)
#include <cuda_runtime.h>
#include <math.h>

// ---------------------------------------------------------------------------
// YoloV1Loss — R16: multi-tile double-buffered TMA pipeline.
// K1: 444 blocks (3/SM, 12 warps/SM), 128 threads; each block strides over
//     ~14 tiles of 128 rows. Buffer k&1 computes while buffer (k+1)&1 streams
//     (TMA issued BEFORE the wait) -> transfer hides compute entirely.
//     mbarrier phase = (k>>1)&1 per buffer; buffer reuse fenced by the
//     end-of-iteration __syncthreads.
// K2: R15 finalize (one coalesced meta pass into smem), nt=6272. PDL kept.
// ---------------------------------------------------------------------------

#define TPB   128
#define RPT   128
#define MAXT  8192
#define NCLS  20
#define FTPB  1024
#define GRIDK 444
#define TILE_BYTES (RPT * 30 * 4)     // 15360 per array per tile

__device__ float4 g_meta[MAXT];            // (csum, noobj, count, 0)
__device__ float  g_contrib[MAXT * RPT];   // rank-compacted per tile

// ---------------- K1: pipelined main pass ----------------
__global__ void __launch_bounds__(TPB) yolo_main(const float* __restrict__ p,
                                                 const float* __restrict__ t,
                                                 int nrows, int nt) {
    extern __shared__ float smem[];
    // buffer b: ps at b*(2*RPT*30), ts at b*(2*RPT*30)+RPT*30
    __shared__ __align__(8) unsigned long long mbar[2];
    __shared__ int   wtot[TPB / 32];
    __shared__ float wredN[TPB / 32];
    __shared__ float wredC[TPB / 32];

    const int tid    = threadIdx.x;
    const int bid    = blockIdx.x;
    const int lane   = tid & 31;
    const int wid    = tid >> 5;
    const int stride = gridDim.x;
    const int nmy    = (nt > bid) ? ((nt - bid + stride - 1) / stride) : 0;

    const unsigned mb0 = (unsigned)__cvta_generic_to_shared(&mbar[0]);
    const unsigned mb1 = (unsigned)__cvta_generic_to_shared(&mbar[1]);
    if (tid == 0) {
        asm volatile("mbarrier.init.shared.b64 [%0], 1;" :: "r"(mb0) : "memory");
        asm volatile("mbarrier.init.shared.b64 [%0], 1;" :: "r"(mb1) : "memory");
    }
    __syncthreads();

    // issue TMA for tile k into buffer k&1 (full tiles only)
    auto stage = [&](int k) {
        const int tile = bid + k * stride;
        const int row0 = tile * RPT;
        if (min(RPT, nrows - row0) == RPT && tid == 0) {
            const int b = k & 1;
            const unsigned mb = b ? mb1 : mb0;
            const unsigned ap = (unsigned)__cvta_generic_to_shared(
                smem + b * (2 * RPT * 30));
            const unsigned at = ap + TILE_BYTES;
            asm volatile("mbarrier.arrive.expect_tx.shared.b64 _, [%0], %1;"
                         :: "r"(mb), "r"(2 * TILE_BYTES) : "memory");
            asm volatile(
                "cp.async.bulk.shared::cta.global.mbarrier::complete_tx::bytes"
                " [%0], [%1], %2, [%3];"
                :: "r"(ap), "l"(p + (size_t)row0 * 30), "r"(TILE_BYTES),
                   "r"(mb) : "memory");
            asm volatile(
                "cp.async.bulk.shared::cta.global.mbarrier::complete_tx::bytes"
                " [%0], [%1], %2, [%3];"
                :: "r"(at), "l"(t + (size_t)row0 * 30), "r"(TILE_BYTES),
                   "r"(mb) : "memory");
        }
    };

    if (nmy > 0) stage(0);

    for (int k = 0; k < nmy; k++) {
        if (k + 1 < nmy) stage(k + 1);          // next tile streams during compute

        const int  b    = k & 1;
        const int  tile = bid + k * stride;
        const int  row0 = tile * RPT;
        const int  rows = min(RPT, nrows - row0);
        float* ps  = smem + b * (2 * RPT * 30);
        float* tsd = ps + RPT * 30;

        if (rows == RPT) {
            // wait for this buffer's phase
            const unsigned mb  = b ? mb1 : mb0;
            const unsigned par = (unsigned)((k >> 1) & 1);
            unsigned done;
            asm volatile(
                "{\n\t.reg .pred pd;\n\t"
                "mbarrier.try_wait.parity.acquire.cta.shared::cta.b64 pd, [%1], %2;\n\t"
                "selp.b32 %0, 1, 0, pd;\n\t}"
                : "=r"(done) : "r"(mb), "r"(par) : "memory");
            while (!done) {
                asm volatile(
                    "{\n\t.reg .pred pd;\n\t"
                    "mbarrier.try_wait.parity.acquire.cta.shared::cta.b64 pd, [%1], %2, 0x989680;\n\t"
                    "selp.b32 %0, 1, 0, pd;\n\t}"
                    : "=r"(done) : "r"(mb), "r"(par) : "memory");
            }
        } else {
            // tail tile: plain staged loads
            for (int i = tid; i < rows * 30; i += TPB) {
                ps[i]  = p[(size_t)row0 * 30 + i];
                tsd[i] = t[(size_t)row0 * 30 + i];
            }
            __syncthreads();
        }

        // ---- per-row compute ----
        const bool inrange = (tid < rows);
        const float* pr = ps  + tid * 30;
        const float* tr = tsd + tid * 30;

        const float conf = inrange ? tr[4] : -1.0f;
        const bool  cm   = (conf == 1.0f);

        float nv = 0.0f;
        if (inrange && conf == 0.0f) {
            const float d0 = pr[4] - tr[4];
            const float d1 = pr[9] - tr[9];
            nv = 0.5f * (d0 * d0 + d1 * d1);
        }

        float cv = 0.0f;
        if (cm) {
            const float C = 1.0f / 7.0f;
            const float tb0 = tr[0] * tr[0], tb1 = tr[1] * tr[1];
            const float tb2 = tr[2] * tr[2], tb3 = tr[3] * tr[3];
            const float tax = tb0 * C - tb2, tay = tb1 * C - tb3;
            const float tbx = tax * C + tb2, tby = tay * C + tb3;
            const float at2 = (tbx - tax) * (tby - tay);

            float iou0 = 0.0f, iou1 = 0.0f;
#pragma unroll
            for (int bb = 0; bb < 2; bb++) {
                const float x = pr[bb * 5 + 0], y = pr[bb * 5 + 1];
                const float w = pr[bb * 5 + 2], h = pr[bb * 5 + 3];
                const float ax = x * C - w,  ay = y * C - h;
                const float bx = ax * C + w, by = ay * C + h;
                const float iw = fmaxf(fminf(bx, tbx) - fmaxf(ax, tax), 0.0f);
                const float ih = fmaxf(fminf(by, tby) - fmaxf(ay, tay), 0.0f);
                const float inter = iw * ih;
                const float ap2 = (bx - ax) * (by - ay);
                const float iou = inter / (ap2 + at2 - inter);
                if (bb == 0) iou0 = iou; else iou1 = iou;
            }
            int idx;
            if (isnan(iou0))      idx = 0;   // numpy argmax semantics
            else if (isnan(iou1)) idx = 1;
            else                  idx = (iou1 > iou0) ? 1 : 0;

            const int ob = idx * 5;
            const float s0 = pr[ob + 0] - tr[0];
            const float s1 = pr[ob + 1] - tr[1];
            const float s2 = pr[ob + 2] - tr[2];
            const float s3 = pr[ob + 3] - tr[3];

            float best = tr[10];
            float clp  = pr[10];
#pragma unroll
            for (int j = 1; j < NCLS; j++) {
                const float v = tr[10 + j];
                const bool  u = (v > best);
                best = u ? v : best;
                clp  = u ? pr[10 + j] : clp;
            }
            const float clv = clp - 1.0f;

            cv = 5.0f * (s0 * s0 + s1 * s1 + s2 * s2 + s3 * s3 +
                         2.0f * clv * clv);
        }

        // rank merge + reductions
        const unsigned bal = __ballot_sync(0xffffffffu, cm);
        unsigned le_mask;
        asm("mov.u32 %0, %%lanemask_le;" : "=r"(le_mask));
        const int inc = __popc(bal & le_mask);
        if (lane == 31) wtot[wid] = __popc(bal);
        __syncthreads();
        int woff = 0, ctot = 0;
#pragma unroll
        for (int i = 0; i < TPB / 32; i++) {
            const int c = wtot[i];
            if (i < wid) woff += c;
            ctot += c;
        }
        if (cm) g_contrib[tile * RPT + (woff + inc - 1)] = cv;

        float nvr = nv, cvr = cv;
#pragma unroll
        for (int o = 16; o > 0; o >>= 1) {
            nvr += __shfl_down_sync(0xffffffffu, nvr, o);
            cvr += __shfl_down_sync(0xffffffffu, cvr, o);
        }
        if (lane == 0) { wredN[wid] = nvr; wredC[wid] = cvr; }
        __syncthreads();
        if (tid == 0) {
            float sn = 0.0f, sc = 0.0f;
#pragma unroll
            for (int i = 0; i < TPB / 32; i++) { sn += wredN[i]; sc += wredC[i]; }
            g_meta[tile] = make_float4(sc, sn, __int_as_float(ctot), 0.0f);
        }
        __syncthreads();     // buffer + shared scratch free for reuse
    }

    asm volatile("griddepcontrol.launch_dependents;" ::: "memory");
}

// ---------------- K2: finalize (PDL, one coalesced meta pass) ----------------
__global__ void __launch_bounds__(FTPB) yolo_finalize(float* __restrict__ out,
                                                      int nt) {
    asm volatile("griddepcontrol.wait;" ::: "memory");

    extern __shared__ float fsm[];
    float* scs  = fsm;                    // nt floats (csum)
    float* sno  = fsm + nt;               // nt floats (noobj)
    int*   scnt = (int*)(fsm + 2 * nt);   // nt ints

    const int tid  = threadIdx.x;
    const int lane = tid & 31;
    const int wid  = tid >> 5;

    for (int i = tid; i < nt; i += FTPB) {
        const float4 m = g_meta[i];
        scs[i]  = m.x;
        sno[i]  = m.y;
        scnt[i] = __float_as_int(m.z);
    }
    __syncthreads();

    const int CH = (nt + FTPB - 1) / FTPB;
    const int i0 = tid * CH;
    int lsum = 0;
    for (int k = 0; k < CH; k++) {
        const int i = i0 + k;
        if (i < nt) lsum += scnt[i];
    }
    int incs = lsum;
#pragma unroll
    for (int o = 1; o < 32; o <<= 1) {
        const int x = __shfl_up_sync(0xffffffffu, incs, o);
        if (lane >= o) incs += x;
    }
    const int ex = incs - lsum;

    __shared__ int ws[FTPB / 32];
    __shared__ int wsx[FTPB / 32 + 1];
    __shared__ int s_bb, s_take;
    if (tid == 0) { s_bb = -1; s_take = 0; }
    if (lane == 31) ws[wid] = incs;
    __syncthreads();
    if (wid == 0) {
        int v = ws[lane];
#pragma unroll
        for (int o = 1; o < 32; o <<= 1) {
            const int x = __shfl_up_sync(0xffffffffu, v, o);
            if (lane >= o) v += x;
        }
        wsx[lane + 1] = v;
        if (lane == 0) wsx[0] = 0;
    }
    __syncthreads();
    const int half = wsx[FTPB / 32] >> 1;       // n_obj // 2

    double acc = 0.0;
    {
        int pre = wsx[wid] + ex;
        for (int k = 0; k < CH; k++) {
            const int i = i0 + k;
            if (i < nt) {
                const int cnt  = scnt[i];
                const int take = min(cnt, max(0, half - pre));
                if (take == cnt)    acc += (double)scs[i];
                else if (take > 0) { s_bb = i; s_take = take; }
                acc += (double)sno[i];
                pre += cnt;
            }
        }
    }
    __syncthreads();

    if (s_bb >= 0) {
        const float* cb = g_contrib + s_bb * RPT;
        for (int i = tid; i < s_take; i += FTPB) acc += (double)cb[i];
    }

#pragma unroll
    for (int o = 16; o > 0; o >>= 1)
        acc += __shfl_down_sync(0xffffffffu, acc, o);
    __shared__ double sd[FTPB / 32];
    if (lane == 0) sd[wid] = acc;
    __syncthreads();
    if (tid == 0) {
        double s = 0.0;
#pragma unroll
        for (int i = 0; i < FTPB / 32; i++) s += sd[i];
        out[0] = (float)s;
    }
}

// ---------------------------------------------------------------------------
extern "C" void kernel_launch(void* const* d_in, const int* in_sizes, int n_in,
                              void* d_out, int out_size) {
    const float* p = (const float*)d_in[0];
    const float* t = (const float*)d_in[1];

    const int nrows = in_sizes[0] / 30;
    const int nt    = (nrows + RPT - 1) / RPT;          // 6272

    const int smem_main = 2 * 2 * RPT * 30 * (int)sizeof(float); // 61440
    cudaFuncSetAttribute(yolo_main,
                         cudaFuncAttributeMaxDynamicSharedMemorySize,
                         smem_main);

    const int smem_fin = 3 * nt * (int)sizeof(float);   // 75264
    cudaFuncSetAttribute(yolo_finalize,
                         cudaFuncAttributeMaxDynamicSharedMemorySize,
                         smem_fin);

    const int grid = (nt < GRIDK) ? nt : GRIDK;
    yolo_main<<<grid, TPB, smem_main>>>(p, t, nrows, nt);

    cudaLaunchConfig_t cfg = {};
    cfg.gridDim          = dim3(1, 1, 1);
    cfg.blockDim         = dim3(FTPB, 1, 1);
    cfg.dynamicSmemBytes = smem_fin;
    cfg.stream           = 0;
    cudaLaunchAttribute attr[1];
    attr[0].id = cudaLaunchAttributeProgrammaticStreamSerialization;
    attr[0].val.programmaticStreamSerializationAllowed = 1;
    cfg.attrs    = attr;
    cfg.numAttrs = 1;
    float* outf = (float*)d_out;
    cudaLaunchKernelEx(&cfg, yolo_finalize, outf, nt);
}

// round 17
// speedup vs baseline: 1.0900x; 1.0900x over previous
#include <cuda_runtime.h>
#include <math.h>

// ---------------------------------------------------------------------------
// YoloV1Loss — R17 = R13 (best) + L2 prefetch of next-wave tile.
// R16 showed smem double-buffering can't be afforded at useful burst sizes.
// Instead: overlap at the L2 level. Each block fires
// cp.async.bulk.prefetch.L2.global for tile bid+444 (one wave ahead,
// 444 = 148 SMs x 3 resident blocks). DRAM streams continuously into L2
// during compute phases; next wave's TMA then completes from L2.
// Zero change to burst length (30720B), occupancy (3/SM), or compute.
// ---------------------------------------------------------------------------

#define TPB   256
#define RPT   256
#define MAXT  4096
#define NCLS  20
#define FTPB  1024
#define WAVE  444
#define TILE_BYTES (RPT * 30 * 4)     // 30720 per array

__device__ float4 g_meta[MAXT];            // (csum, noobj, count, 0)
__device__ float  g_contrib[MAXT * RPT];   // rank-compacted per tile

// ---------------- K1: main pass ----------------
__global__ void __launch_bounds__(TPB) yolo_main(const float* __restrict__ p,
                                                 const float* __restrict__ t,
                                                 int nrows) {
    extern __shared__ float smem[];
    float* ps  = smem;                 // RPT*30 floats
    float* tsd = smem + RPT * 30;      // RPT*30 floats
    __shared__ __align__(8) unsigned long long mbar;
    __shared__ int   wtot[TPB / 32];
    __shared__ float wredN[TPB / 32];
    __shared__ float wredC[TPB / 32];

    const int tid  = threadIdx.x;
    const int bid  = blockIdx.x;
    const int row0 = bid * RPT;
    const int lane = tid & 31;
    const int wid  = tid >> 5;
    const int rows = min(RPT, nrows - row0);
    const size_t base = (size_t)row0 * 30;

    if (rows == RPT) {
        // ---- TMA bulk staging: 2 contiguous 30720B transfers ----
        const unsigned mb = (unsigned)__cvta_generic_to_shared(&mbar);
        const unsigned ap = (unsigned)__cvta_generic_to_shared(ps);
        const unsigned at = (unsigned)__cvta_generic_to_shared(tsd);
        if (tid == 0) {
            asm volatile("mbarrier.init.shared.b64 [%0], 1;"
                         :: "r"(mb) : "memory");
        }
        __syncthreads();
        if (tid == 0) {
            asm volatile("mbarrier.arrive.expect_tx.shared.b64 _, [%0], %1;"
                         :: "r"(mb), "r"(2 * TILE_BYTES) : "memory");
            asm volatile(
                "cp.async.bulk.shared::cta.global.mbarrier::complete_tx::bytes"
                " [%0], [%1], %2, [%3];"
                :: "r"(ap), "l"(p + base), "r"(TILE_BYTES), "r"(mb) : "memory");
            asm volatile(
                "cp.async.bulk.shared::cta.global.mbarrier::complete_tx::bytes"
                " [%0], [%1], %2, [%3];"
                :: "r"(at), "l"(t + base), "r"(TILE_BYTES), "r"(mb) : "memory");

            // ---- L2 prefetch for the tile this SM slot runs next wave ----
            const int pf = bid + WAVE;
            if ((size_t)(pf + 1) * RPT <= (size_t)nrows) {
                const float* pp = p + (size_t)pf * RPT * 30;
                const float* tp = t + (size_t)pf * RPT * 30;
                asm volatile("cp.async.bulk.prefetch.L2.global [%0], %1;"
                             :: "l"(pp), "r"(TILE_BYTES));
                asm volatile("cp.async.bulk.prefetch.L2.global [%0], %1;"
                             :: "l"(tp), "r"(TILE_BYTES));
            }
        }
        // all threads wait for completion (phase 0), acquire semantics
        {
            unsigned done;
            asm volatile(
                "{\n\t.reg .pred pd;\n\t"
                "mbarrier.try_wait.parity.acquire.cta.shared::cta.b64 pd, [%1], 0;\n\t"
                "selp.b32 %0, 1, 0, pd;\n\t}"
                : "=r"(done) : "r"(mb) : "memory");
            while (!done) {
                asm volatile(
                    "{\n\t.reg .pred pd;\n\t"
                    "mbarrier.try_wait.parity.acquire.cta.shared::cta.b64 pd, [%1], 0, 0x989680;\n\t"
                    "selp.b32 %0, 1, 0, pd;\n\t}"
                    : "=r"(done) : "r"(mb) : "memory");
            }
        }
    } else {
        // ---- tail fallback: plain staged loads ----
        for (int i = tid; i < rows * 30; i += TPB) {
            ps[i]  = p[base + i];
            tsd[i] = t[base + i];
        }
    }
    __syncthreads();

    const bool inrange = (tid < rows);
    const float* pr = ps  + tid * 30;
    const float* tr = tsd + tid * 30;

    const float conf = inrange ? tr[4] : -1.0f;
    const bool  cm   = (conf == 1.0f);

    // in-block inclusive rank of coord rows
    const unsigned bal = __ballot_sync(0xffffffffu, cm);
    unsigned le_mask;
    asm("mov.u32 %0, %%lanemask_le;" : "=r"(le_mask));
    const int inc = __popc(bal & le_mask);
    if (lane == 31) wtot[wid] = __popc(bal);
    __syncthreads();
    int woff = 0, ctot = 0;
#pragma unroll
    for (int i = 0; i < TPB / 32; i++) {
        const int c = wtot[i];
        if (i < wid) woff += c;
        ctot += c;
    }

    // noobj term
    float nv = 0.0f;
    if (inrange && conf == 0.0f) {
        const float d0 = pr[4] - tr[4];
        const float d1 = pr[9] - tr[9];
        nv = 0.5f * (d0 * d0 + d1 * d1);
    }

    // coord term (global gate resolved in K2)
    float cv = 0.0f;
    if (cm) {
        const float C = 1.0f / 7.0f;
        const float tb0 = tr[0] * tr[0], tb1 = tr[1] * tr[1];
        const float tb2 = tr[2] * tr[2], tb3 = tr[3] * tr[3];
        const float tax = tb0 * C - tb2, tay = tb1 * C - tb3;
        const float tbx = tax * C + tb2, tby = tay * C + tb3;
        const float at2 = (tbx - tax) * (tby - tay);

        float iou0 = 0.0f, iou1 = 0.0f;
#pragma unroll
        for (int b = 0; b < 2; b++) {
            const float x = pr[b * 5 + 0], y = pr[b * 5 + 1];
            const float w = pr[b * 5 + 2], h = pr[b * 5 + 3];
            const float ax = x * C - w,  ay = y * C - h;
            const float bx = ax * C + w, by = ay * C + h;
            const float iw = fmaxf(fminf(bx, tbx) - fmaxf(ax, tax), 0.0f);
            const float ih = fmaxf(fminf(by, tby) - fmaxf(ay, tay), 0.0f);
            const float inter = iw * ih;
            const float ap2 = (bx - ax) * (by - ay);
            const float iou = inter / (ap2 + at2 - inter);
            if (b == 0) iou0 = iou; else iou1 = iou;
        }
        int idx;
        if (isnan(iou0))      idx = 0;   // numpy argmax: NaN wins, first occ.
        else if (isnan(iou1)) idx = 1;
        else                  idx = (iou1 > iou0) ? 1 : 0;

        const int ob = idx * 5;
        const float s0 = pr[ob + 0] - tr[0];
        const float s1 = pr[ob + 1] - tr[1];
        const float s2 = pr[ob + 2] - tr[2];
        const float s3 = pr[ob + 3] - tr[3];

        // class argmax from smem (first strict max) + paired p-select
        float best = tr[10];
        float clp  = pr[10];
#pragma unroll
        for (int j = 1; j < NCLS; j++) {
            const float v = tr[10 + j];
            const bool  u = (v > best);
            best = u ? v : best;
            clp  = u ? pr[10 + j] : clp;
        }
        const float clv = clp - 1.0f;

        cv = 5.0f * (s0 * s0 + s1 * s1 + s2 * s2 + s3 * s3 + 2.0f * clv * clv);
        g_contrib[bid * RPT + (woff + inc - 1)] = cv;
    }

    // block reductions: noobj + coord sums
#pragma unroll
    for (int o = 16; o > 0; o >>= 1) {
        nv += __shfl_down_sync(0xffffffffu, nv, o);
        cv += __shfl_down_sync(0xffffffffu, cv, o);
    }
    if (lane == 0) { wredN[wid] = nv; wredC[wid] = cv; }
    __syncthreads();
    if (tid == 0) {
        float sn = 0.0f, sc = 0.0f;
#pragma unroll
        for (int i = 0; i < TPB / 32; i++) { sn += wredN[i]; sc += wredC[i]; }
        g_meta[bid] = make_float4(sc, sn, __int_as_float(ctot), 0.0f);
    }
    __syncthreads();

    asm volatile("griddepcontrol.launch_dependents;" ::: "memory");
}

// ---------------- K2: finalize (PDL, one coalesced meta pass) ----------------
__global__ void __launch_bounds__(FTPB) yolo_finalize(float* __restrict__ out,
                                                      int nt) {
    asm volatile("griddepcontrol.wait;" ::: "memory");

    extern __shared__ float fsm[];
    float* scs  = fsm;                    // nt floats (csum)
    float* sno  = fsm + nt;               // nt floats (noobj)
    int*   scnt = (int*)(fsm + 2 * nt);   // nt ints

    const int tid  = threadIdx.x;
    const int lane = tid & 31;
    const int wid  = tid >> 5;

    for (int i = tid; i < nt; i += FTPB) {
        const float4 m = g_meta[i];
        scs[i]  = m.x;
        sno[i]  = m.y;
        scnt[i] = __float_as_int(m.z);
    }
    __syncthreads();

    const int CH = (nt + FTPB - 1) / FTPB;
    const int i0 = tid * CH;
    int lsum = 0;
    for (int k = 0; k < CH; k++) {
        const int i = i0 + k;
        if (i < nt) lsum += scnt[i];
    }
    int incs = lsum;
#pragma unroll
    for (int o = 1; o < 32; o <<= 1) {
        const int x = __shfl_up_sync(0xffffffffu, incs, o);
        if (lane >= o) incs += x;
    }
    const int ex = incs - lsum;

    __shared__ int ws[FTPB / 32];
    __shared__ int wsx[FTPB / 32 + 1];
    __shared__ int s_bb, s_take;
    if (tid == 0) { s_bb = -1; s_take = 0; }
    if (lane == 31) ws[wid] = incs;
    __syncthreads();
    if (wid == 0) {
        int v = ws[lane];
#pragma unroll
        for (int o = 1; o < 32; o <<= 1) {
            const int x = __shfl_up_sync(0xffffffffu, v, o);
            if (lane >= o) v += x;
        }
        wsx[lane + 1] = v;
        if (lane == 0) wsx[0] = 0;
    }
    __syncthreads();
    const int half = wsx[FTPB / 32] >> 1;       // n_obj // 2

    double acc = 0.0;
    {
        int pre = wsx[wid] + ex;
        for (int k = 0; k < CH; k++) {
            const int i = i0 + k;
            if (i < nt) {
                const int cnt  = scnt[i];
                const int take = min(cnt, max(0, half - pre));
                if (take == cnt)    acc += (double)scs[i];
                else if (take > 0) { s_bb = i; s_take = take; }
                acc += (double)sno[i];
                pre += cnt;
            }
        }
    }
    __syncthreads();

    if (s_bb >= 0) {                              // <=RPT-float partial
        const float* cb = g_contrib + s_bb * RPT;
        for (int i = tid; i < s_take; i += FTPB) acc += (double)cb[i];
    }

#pragma unroll
    for (int o = 16; o > 0; o >>= 1)
        acc += __shfl_down_sync(0xffffffffu, acc, o);
    __shared__ double sd[FTPB / 32];
    if (lane == 0) sd[wid] = acc;
    __syncthreads();
    if (tid == 0) {
        double s = 0.0;
#pragma unroll
        for (int i = 0; i < FTPB / 32; i++) s += sd[i];
        out[0] = (float)s;
    }
}

// ---------------------------------------------------------------------------
extern "C" void kernel_launch(void* const* d_in, const int* in_sizes, int n_in,
                              void* d_out, int out_size) {
    const float* p = (const float*)d_in[0];
    const float* t = (const float*)d_in[1];

    const int nrows = in_sizes[0] / 30;
    const int nt    = (nrows + RPT - 1) / RPT;          // 3136

    const int smem_main = 2 * RPT * 30 * (int)sizeof(float);   // 61440
    cudaFuncSetAttribute(yolo_main,
                         cudaFuncAttributeMaxDynamicSharedMemorySize,
                         smem_main);

    const int smem_fin = 3 * nt * (int)sizeof(float);           // 37632
    cudaFuncSetAttribute(yolo_finalize,
                         cudaFuncAttributeMaxDynamicSharedMemorySize,
                         smem_fin);

    yolo_main<<<nt, TPB, smem_main>>>(p, t, nrows);

    cudaLaunchConfig_t cfg = {};
    cfg.gridDim          = dim3(1, 1, 1);
    cfg.blockDim         = dim3(FTPB, 1, 1);
    cfg.dynamicSmemBytes = smem_fin;
    cfg.stream           = 0;
    cudaLaunchAttribute attr[1];
    attr[0].id = cudaLaunchAttributeProgrammaticStreamSerialization;
    attr[0].val.programmaticStreamSerializationAllowed = 1;
    cfg.attrs    = attr;
    cfg.numAttrs = 1;
    float* outf = (float*)d_out;
    cudaLaunchKernelEx(&cfg, yolo_finalize, outf, nt);
}